// round 5
// baseline (speedup 1.0000x reference)
#include <cuda_runtime.h>
#include <cstdint>

#define N_NODES 10000
#define N_EDGES 320000
#define F_IN 512
#define HID 256

// ---------------- device scratch (static, no allocation) ----------------
__device__ __align__(16) int   g_cnt[N_NODES];       // indegree
__device__ __align__(16) int   g_off[N_NODES];       // exclusive prefix
__device__ __align__(16) int   g_pos[N_NODES];       // scatter cursor
__device__ __align__(16) float g_rdeg[N_NODES];      // rsqrt(max(deg,1))
__device__ __align__(16) int   g_csr_src[N_EDGES];   // src ids grouped by dst
__device__ __align__(16) float g_H0[(size_t)N_NODES * HID];
__device__ __align__(16) float g_Z[N_NODES * 2];

// ---------------- packed f32x2 helpers ----------------
#define FMA2(d, a, b) asm("fma.rn.f32x2 %0, %1, %2, %0;" : "+l"(d) : "l"(a), "l"(b))
#define DUP2(d, s)    asm("mov.b64 %0, {%1, %1};" : "=l"(d) : "r"(s))
#define UNPK2(lo, hi, s) asm("mov.b64 {%0, %1}, %2;" : "=f"(lo), "=f"(hi) : "l"(s))

// ---------------- CSR build ----------------
__global__ void zero_kernel() {
    int i = blockIdx.x * blockDim.x + threadIdx.x;
    if (i < N_NODES) g_cnt[i] = 0;
}

__global__ void deg_kernel(const int* __restrict__ ei) {
    int base = (blockIdx.x * blockDim.x + threadIdx.x) * 4;
    #pragma unroll
    for (int i = 0; i < 4; i++) {
        int e = base + i;
        if (e < N_EDGES) atomicAdd(&g_cnt[ei[N_EDGES + e]], 1);
    }
}

#define SCAN_THREADS 1024
#define SCAN_CHUNK 10
__global__ __launch_bounds__(SCAN_THREADS) void scan_kernel() {
    __shared__ int partial[SCAN_THREADS];
    int tid = threadIdx.x;
    int base = tid * SCAN_CHUNK;
    int local[SCAN_CHUNK];
    int sum = 0;
    #pragma unroll
    for (int i = 0; i < SCAN_CHUNK; i++) {
        int idx = base + i;
        int v = (idx < N_NODES) ? g_cnt[idx] : 0;
        local[i] = sum;
        sum += v;
    }
    partial[tid] = sum;
    __syncthreads();
    for (int off = 1; off < SCAN_THREADS; off <<= 1) {
        int v = 0;
        if (tid >= off) v = partial[tid - off];
        __syncthreads();
        if (tid >= off) partial[tid] += v;
        __syncthreads();
    }
    int prev = (tid == 0) ? 0 : partial[tid - 1];
    #pragma unroll
    for (int i = 0; i < SCAN_CHUNK; i++) {
        int idx = base + i;
        if (idx < N_NODES) {
            int o = prev + local[i];
            g_off[idx] = o;
            g_pos[idx] = o;
            g_rdeg[idx] = rsqrtf(fmaxf((float)g_cnt[idx], 1.0f));
        }
    }
}

__global__ void scatter_kernel(const int* __restrict__ ei) {
    int base = (blockIdx.x * blockDim.x + threadIdx.x) * 4;
    #pragma unroll
    for (int i = 0; i < 4; i++) {
        int e = base + i;
        if (e < N_EDGES) {
            int s = ei[e];
            int d = ei[N_EDGES + e];
            int pos = atomicAdd(&g_pos[d], 1);
            g_csr_src[pos] = s;
        }
    }
}

// ---------------- SGEMM (FFMA2): H0 = feature[10000,512] @ W1[512,256] + b1 ----------------
#define BM 128
#define BN 128
#define BK 16
// 256 threads: 16x16, each thread 8 rows (4 M-pairs) x 8 cols

__global__ __launch_bounds__(256, 2) void gemm1_kernel(
    const float* __restrict__ A,   // [10000, 512]
    const float* __restrict__ B,   // [512, 256]
    const float* __restrict__ bias // [256]
) {
    __shared__ float As[BK][BM + 4];   // transposed: As[k][m]; stride 132*4=528B (16B mult)
    __shared__ float Bs[BK][BN + 4];
    const int M = N_NODES, K = F_IN, NN = HID;

    int bm = blockIdx.y * BM;
    int bn = blockIdx.x * BN;
    int tid = threadIdx.x;
    int tcol = tid & 15;   // 8 output cols each
    int trow = tid >> 4;   // 8 output rows each (4 packed pairs)

    unsigned long long acc2[4][8];
    #pragma unroll
    for (int i = 0; i < 4; i++)
        #pragma unroll
        for (int j = 0; j < 8; j++) acc2[i][j] = 0ULL;

    for (int k0 = 0; k0 < K; k0 += BK) {
        // load A tile: 128 rows x 16 K = 512 float4; 2 per thread (transposed store)
        #pragma unroll
        for (int i = 0; i < 2; i++) {
            int f = tid + 256 * i;
            int r = f >> 2;
            int c4 = f & 3;
            int grow = bm + r;
            float4 v = make_float4(0.f, 0.f, 0.f, 0.f);
            if (grow < M)
                v = *(const float4*)(A + (size_t)grow * K + k0 + c4 * 4);
            As[c4 * 4 + 0][r] = v.x;
            As[c4 * 4 + 1][r] = v.y;
            As[c4 * 4 + 2][r] = v.z;
            As[c4 * 4 + 3][r] = v.w;
        }
        // load B tile: 16 K-rows x 128 cols = 512 float4; 2 per thread
        #pragma unroll
        for (int i = 0; i < 2; i++) {
            int f = tid + 256 * i;
            int r = f >> 5;
            int c4 = f & 31;
            float4 v = *(const float4*)(B + (size_t)(k0 + r) * NN + bn + c4 * 4);
            *(float4*)(&Bs[r][c4 * 4]) = v;
        }
        __syncthreads();

        #pragma unroll
        for (int k = 0; k < BK; k++) {
            // A fragment: 8 consecutive M rows = 4 f32x2 pairs (16B-aligned LDS.128)
            ulonglong2 a01 = *(const ulonglong2*)(&As[k][trow * 8]);
            ulonglong2 a23 = *(const ulonglong2*)(&As[k][trow * 8 + 4]);
            unsigned long long a2[4] = {a01.x, a01.y, a23.x, a23.y};
            // B fragment: 8 scalars, duplicated into both halves
            float4 b0 = *(const float4*)(&Bs[k][tcol * 8]);
            float4 b1 = *(const float4*)(&Bs[k][tcol * 8 + 4]);
            float bf[8] = {b0.x, b0.y, b0.z, b0.w, b1.x, b1.y, b1.z, b1.w};
            unsigned long long bd[8];
            #pragma unroll
            for (int j = 0; j < 8; j++) DUP2(bd[j], __float_as_uint(bf[j]));
            #pragma unroll
            for (int i = 0; i < 4; i++)
                #pragma unroll
                for (int j = 0; j < 8; j++)
                    FMA2(acc2[i][j], a2[i], bd[j]);
        }
        __syncthreads();
    }

    // store with bias
    float4 bva = *(const float4*)(bias + bn + tcol * 8);
    float4 bvb = *(const float4*)(bias + bn + tcol * 8 + 4);
    float bb[8] = {bva.x, bva.y, bva.z, bva.w, bvb.x, bvb.y, bvb.z, bvb.w};
    #pragma unroll
    for (int pi = 0; pi < 4; pi++) {
        float lo[8], hi[8];
        #pragma unroll
        for (int j = 0; j < 8; j++) UNPK2(lo[j], hi[j], acc2[pi][j]);
        int rlo = bm + trow * 8 + pi * 2;
        int rhi = rlo + 1;
        if (rlo < M) {
            float4 o0 = make_float4(lo[0] + bb[0], lo[1] + bb[1], lo[2] + bb[2], lo[3] + bb[3]);
            float4 o1 = make_float4(lo[4] + bb[4], lo[5] + bb[5], lo[6] + bb[6], lo[7] + bb[7]);
            *(float4*)(g_H0 + (size_t)rlo * NN + bn + tcol * 8) = o0;
            *(float4*)(g_H0 + (size_t)rlo * NN + bn + tcol * 8 + 4) = o1;
        }
        if (rhi < M) {
            float4 o0 = make_float4(hi[0] + bb[0], hi[1] + bb[1], hi[2] + bb[2], hi[3] + bb[3]);
            float4 o1 = make_float4(hi[4] + bb[4], hi[5] + bb[5], hi[6] + bb[6], hi[7] + bb[7]);
            *(float4*)(g_H0 + (size_t)rhi * NN + bn + tcol * 8) = o0;
            *(float4*)(g_H0 + (size_t)rhi * NN + bn + tcol * 8 + 4) = o1;
        }
    }
}

// ---------------- fused agg1 + relu + W2 + b2 -> Z (warp per dst) ----------------
__global__ __launch_bounds__(256) void fusedZ_kernel(const float* __restrict__ W2,
                                                     const float* __restrict__ b2) {
    int gw = (blockIdx.x * blockDim.x + threadIdx.x) >> 5;
    int lane = threadIdx.x & 31;
    if (gw >= N_NODES) return;

    int start = g_off[gw];
    int end = start + g_cnt[gw];
    float rdd = g_rdeg[gw];

    int cA = 4 * lane;
    int cB = 128 + 4 * lane;
    float w0a[4], w1a[4], w0b[4], w1b[4];
    #pragma unroll
    for (int j = 0; j < 4; j++) {
        w0a[j] = __ldg(&W2[(cA + j) * 2 + 0]);
        w1a[j] = __ldg(&W2[(cA + j) * 2 + 1]);
        w0b[j] = __ldg(&W2[(cB + j) * 2 + 0]);
        w1b[j] = __ldg(&W2[(cB + j) * 2 + 1]);
    }

    float acc[8] = {};
    int p = start;
    for (; p + 4 <= end; p += 4) {
        int s0 = g_csr_src[p], s1 = g_csr_src[p + 1];
        int s2 = g_csr_src[p + 2], s3 = g_csr_src[p + 3];
        float n0 = rdd * g_rdeg[s0], n1 = rdd * g_rdeg[s1];
        float n2 = rdd * g_rdeg[s2], n3 = rdd * g_rdeg[s3];
        const float4* r0 = (const float4*)(g_H0 + (size_t)s0 * HID);
        const float4* r1 = (const float4*)(g_H0 + (size_t)s1 * HID);
        const float4* r2 = (const float4*)(g_H0 + (size_t)s2 * HID);
        const float4* r3 = (const float4*)(g_H0 + (size_t)s3 * HID);
        float4 a0 = r0[lane], a1 = r0[lane + 32];
        float4 b0 = r1[lane], b1 = r1[lane + 32];
        float4 c0 = r2[lane], c1 = r2[lane + 32];
        float4 d0 = r3[lane], d1 = r3[lane + 32];
        acc[0] += a0.x * n0 + b0.x * n1 + c0.x * n2 + d0.x * n3;
        acc[1] += a0.y * n0 + b0.y * n1 + c0.y * n2 + d0.y * n3;
        acc[2] += a0.z * n0 + b0.z * n1 + c0.z * n2 + d0.z * n3;
        acc[3] += a0.w * n0 + b0.w * n1 + c0.w * n2 + d0.w * n3;
        acc[4] += a1.x * n0 + b1.x * n1 + c1.x * n2 + d1.x * n3;
        acc[5] += a1.y * n0 + b1.y * n1 + c1.y * n2 + d1.y * n3;
        acc[6] += a1.z * n0 + b1.z * n1 + c1.z * n2 + d1.z * n3;
        acc[7] += a1.w * n0 + b1.w * n1 + c1.w * n2 + d1.w * n3;
    }
    for (; p < end; p++) {
        int s0 = g_csr_src[p];
        float n0 = rdd * g_rdeg[s0];
        const float4* r0 = (const float4*)(g_H0 + (size_t)s0 * HID);
        float4 a0 = r0[lane], a1 = r0[lane + 32];
        acc[0] += a0.x * n0; acc[1] += a0.y * n0;
        acc[2] += a0.z * n0; acc[3] += a0.w * n0;
        acc[4] += a1.x * n0; acc[5] += a1.y * n0;
        acc[6] += a1.z * n0; acc[7] += a1.w * n0;
    }

    float z0 = 0.f, z1 = 0.f;
    #pragma unroll
    for (int j = 0; j < 4; j++) {
        float xa = fmaxf(acc[j], 0.f);
        float xb = fmaxf(acc[4 + j], 0.f);
        z0 += xa * w0a[j] + xb * w0b[j];
        z1 += xa * w1a[j] + xb * w1b[j];
    }
    #pragma unroll
    for (int o = 16; o; o >>= 1) {
        z0 += __shfl_down_sync(0xFFFFFFFFu, z0, o);
        z1 += __shfl_down_sync(0xFFFFFFFFu, z1, o);
    }
    if (lane == 0) {
        g_Z[2 * gw + 0] = z0 + b2[0];
        g_Z[2 * gw + 1] = z1 + b2[1];
    }
}

// ---------------- fused agg2 + hyperbolic lift + Poincare projection ----------------
__global__ __launch_bounds__(256) void fusedU_kernel(const float* __restrict__ scale,
                                                     float* __restrict__ out) {
    int gw = (blockIdx.x * blockDim.x + threadIdx.x) >> 5;
    int lane = threadIdx.x & 31;
    if (gw >= N_NODES) return;

    int start = g_off[gw];
    int end = start + g_cnt[gw];
    float rdd = g_rdeg[gw];

    float u0 = 0.f, u1 = 0.f;
    for (int p = start + lane; p < end; p += 32) {
        int s = g_csr_src[p];
        float nm = rdd * g_rdeg[s];
        float2 z = *(const float2*)(g_Z + 2 * s);
        u0 += z.x * nm;
        u1 += z.y * nm;
    }
    #pragma unroll
    for (int o = 16; o; o >>= 1) {
        u0 += __shfl_down_sync(0xFFFFFFFFu, u0, o);
        u1 += __shfl_down_sync(0xFFFFFFFFu, u1, o);
    }
    if (lane == 0) {
        float un = sqrtf(u0 * u0 + u1 * u1);
        un = fmaxf(un, 1e-15f);
        float ch = coshf(un);
        float sh = sinhf(un);
        float inv = 1.0f / (un * (1.0f + ch));
        float p0 = sh * u0 * inv;
        float p1 = sh * u1 * inv;
        float pn = fmaxf(sqrtf(p0 * p0 + p1 * p1), 1e-12f);
        const float MIN_SCALE = 2.0f * (0.999f / 3.0f);
        const float MAX_SCALE = 0.999f;
        float s = fminf(fmaxf(scale[0], MIN_SCALE), MAX_SCALE);
        p0 = p0 / pn * s;
        p1 = p1 / pn * s;
        float nrm = fmaxf(sqrtf(p0 * p0 + p1 * p1), 1e-15f);
        float maxnorm = 1.0f - 1e-15f;
        if (nrm > maxnorm) {
            p0 = p0 / nrm * maxnorm;
            p1 = p1 / nrm * maxnorm;
        }
        out[2 * gw + 0] = p0;
        out[2 * gw + 1] = p1;
    }
}

// ---------------- launch ----------------
extern "C" void kernel_launch(void* const* d_in, const int* in_sizes, int n_in,
                              void* d_out, int out_size) {
    const float* feature = (const float*)d_in[0];
    const int* ei = (const int*)d_in[1];
    const float* W1 = (const float*)d_in[2];
    const float* b1 = (const float*)d_in[3];
    const float* W2 = (const float*)d_in[4];
    const float* b2 = (const float*)d_in[5];
    const float* scale = (const float*)d_in[6];
    float* out = (float*)d_out;

    zero_kernel<<<(N_NODES + 255) / 256, 256>>>();
    deg_kernel<<<(N_EDGES / 4 + 255) / 256, 256>>>(ei);
    scan_kernel<<<1, SCAN_THREADS>>>();
    scatter_kernel<<<(N_EDGES / 4 + 255) / 256, 256>>>(ei);
    {
        dim3 grid(HID / BN, (N_NODES + BM - 1) / BM);  // (2, 79)
        gemm1_kernel<<<grid, 256>>>(feature, W1, b1);
    }
    fusedZ_kernel<<<(N_NODES * 32 + 255) / 256, 256>>>(W2, b2);
    fusedU_kernel<<<(N_NODES * 32 + 255) / 256, 256>>>(scale, out);
}

// round 6
// speedup vs baseline: 1.5423x; 1.5423x over previous
#include <cuda_runtime.h>
#include <cuda_bf16.h>
#include <cstdint>

#define N_NODES 10000
#define N_EDGES 320000
#define F_IN 512
#define HID 256

// ---------------- device scratch (static, no allocation) ----------------
__device__ __align__(16) int   g_cnt[N_NODES];
__device__ __align__(16) int   g_off[N_NODES];
__device__ __align__(16) int   g_pos[N_NODES];
__device__ __align__(16) float g_rdeg[N_NODES];
__device__ __align__(16) int   g_csr_src[N_EDGES];
__device__ __align__(16) float g_H0[(size_t)N_NODES * HID];
__device__ __align__(16) float g_Z[N_NODES * 2];
__device__ __align__(16) __nv_bfloat16 g_Bh[HID * F_IN];  // W1^T hi  [n][k]
__device__ __align__(16) __nv_bfloat16 g_Bl[HID * F_IN];  // W1^T lo  [n][k]

// ---------------- mma/ldmatrix helpers (base ISA, sm_80+) ----------------
#define LDSM_X4(r0, r1, r2, r3, addr) \
    asm volatile("ldmatrix.sync.aligned.m8n8.x4.shared.b16 {%0,%1,%2,%3}, [%4];" \
        : "=r"(r0), "=r"(r1), "=r"(r2), "=r"(r3) : "r"(addr))
#define LDSM_X2(r0, r1, addr) \
    asm volatile("ldmatrix.sync.aligned.m8n8.x2.shared.b16 {%0,%1}, [%2];" \
        : "=r"(r0), "=r"(r1) : "r"(addr))
#define MMA_BF16(d0, d1, d2, d3, a0, a1, a2, a3, b0, b1) \
    asm volatile("mma.sync.aligned.m16n8k16.row.col.f32.bf16.bf16.f32 " \
        "{%0,%1,%2,%3}, {%4,%5,%6,%7}, {%8,%9}, {%0,%1,%2,%3};" \
        : "+f"(d0), "+f"(d1), "+f"(d2), "+f"(d3) \
        : "r"(a0), "r"(a1), "r"(a2), "r"(a3), "r"(b0), "r"(b1))

// ---------------- CSR build ----------------
__global__ void zero_kernel() {
    int i = blockIdx.x * blockDim.x + threadIdx.x;
    if (i < N_NODES) g_cnt[i] = 0;
}

__global__ void deg_kernel(const int* __restrict__ ei) {
    int e = blockIdx.x * blockDim.x + threadIdx.x;
    if (e >= N_EDGES) return;
    atomicAdd(&g_cnt[ei[N_EDGES + e]], 1);
}

#define SCAN_THREADS 1024
#define SCAN_CHUNK 10
__global__ __launch_bounds__(SCAN_THREADS) void scan_kernel() {
    __shared__ int partial[SCAN_THREADS];
    int tid = threadIdx.x;
    int base = tid * SCAN_CHUNK;
    int local[SCAN_CHUNK];
    int sum = 0;
    #pragma unroll
    for (int i = 0; i < SCAN_CHUNK; i++) {
        int idx = base + i;
        int v = (idx < N_NODES) ? g_cnt[idx] : 0;
        local[i] = sum;
        sum += v;
    }
    partial[tid] = sum;
    __syncthreads();
    for (int off = 1; off < SCAN_THREADS; off <<= 1) {
        int v = 0;
        if (tid >= off) v = partial[tid - off];
        __syncthreads();
        if (tid >= off) partial[tid] += v;
        __syncthreads();
    }
    int prev = (tid == 0) ? 0 : partial[tid - 1];
    #pragma unroll
    for (int i = 0; i < SCAN_CHUNK; i++) {
        int idx = base + i;
        if (idx < N_NODES) {
            int o = prev + local[i];
            g_off[idx] = o;
            g_pos[idx] = o;
            g_rdeg[idx] = rsqrtf(fmaxf((float)g_cnt[idx], 1.0f));
        }
    }
}

__global__ void scatter_kernel(const int* __restrict__ ei) {
    int e = blockIdx.x * blockDim.x + threadIdx.x;
    if (e >= N_EDGES) return;
    int s = ei[e];
    int d = ei[N_EDGES + e];
    int pos = atomicAdd(&g_pos[d], 1);
    g_csr_src[pos] = s;
}

// ---------------- prepW: transpose + bf16-split W1 -> g_Bh/g_Bl [n][k] ----------------
__global__ void prepW_kernel(const float* __restrict__ W1) {  // W1[k][n]
    int idx = blockIdx.x * blockDim.x + threadIdx.x;
    if (idx >= F_IN * HID) return;
    int k = idx >> 8;
    int n = idx & 255;
    float x = W1[idx];
    __nv_bfloat16 h = __float2bfloat16_rn(x);
    float r = x - __bfloat162float(h);
    __nv_bfloat16 l = __float2bfloat16_rn(r);
    g_Bh[n * F_IN + k] = h;
    g_Bl[n * F_IN + k] = l;
}

// ---------------- HMMA GEMM: H0 = feature @ W1 + b1 (bf16 3-product split) ----------------
// CTA tile 128x128, 8 warps (2 M x 4 N), warp tile 64x32, K chunks of 32.
// SMEM rows padded to 80B (5 x 16B) -> ldmatrix conflict-free.
#define ROWB 80
#define S_AH 0
#define S_AL 10240
#define S_BH 20480
#define S_BL 30720

__global__ __launch_bounds__(256, 2) void gemm_mma_kernel(
    const float* __restrict__ A,   // [10000, 512]
    const float* __restrict__ bias // [256]
) {
    __shared__ __align__(128) char sm[40960];
    uint32_t sbase = (uint32_t)__cvta_generic_to_shared(sm);

    const int M = N_NODES;
    int tid = threadIdx.x;
    int wid = tid >> 5;
    int lane = tid & 31;
    int wm = wid >> 2;       // 0..1 -> M offset 64*wm
    int wn = wid & 3;        // 0..3 -> N offset 32*wn
    int bm = blockIdx.y * 128;
    int bn = blockIdx.x * 128;

    float acc[4][4][4];
    #pragma unroll
    for (int i = 0; i < 4; i++)
        #pragma unroll
        for (int j = 0; j < 4; j++)
            #pragma unroll
            for (int r = 0; r < 4; r++) acc[i][j][r] = 0.f;

    for (int c = 0; c < 16; c++) {
        int k0 = c * 32;
        // --- A chunk: 128 rows x 32 k fp32 -> bf16 hi/lo ---
        #pragma unroll
        for (int i = 0; i < 2; i++) {
            int idx = tid + 256 * i;
            int r = idx >> 2;
            int seg = idx & 3;             // 8-float segment
            int grow = bm + r;
            float4 v0 = make_float4(0.f, 0.f, 0.f, 0.f), v1 = v0;
            if (grow < M) {
                const float* p = A + (size_t)grow * F_IN + k0 + seg * 8;
                v0 = *(const float4*)p;
                v1 = *(const float4*)(p + 4);
            }
            float vals[8] = {v0.x, v0.y, v0.z, v0.w, v1.x, v1.y, v1.z, v1.w};
            uint32_t hw[4], lw[4];
            #pragma unroll
            for (int q = 0; q < 4; q++) {
                __nv_bfloat16 h0 = __float2bfloat16_rn(vals[2 * q]);
                __nv_bfloat16 h1 = __float2bfloat16_rn(vals[2 * q + 1]);
                float r0 = vals[2 * q] - __bfloat162float(h0);
                float r1 = vals[2 * q + 1] - __bfloat162float(h1);
                __nv_bfloat16 l0 = __float2bfloat16_rn(r0);
                __nv_bfloat16 l1 = __float2bfloat16_rn(r1);
                hw[q] = (uint32_t)*(unsigned short*)&h0 | ((uint32_t)*(unsigned short*)&h1 << 16);
                lw[q] = (uint32_t)*(unsigned short*)&l0 | ((uint32_t)*(unsigned short*)&l1 << 16);
            }
            uint4 hv = make_uint4(hw[0], hw[1], hw[2], hw[3]);
            uint4 lv = make_uint4(lw[0], lw[1], lw[2], lw[3]);
            int off = r * ROWB + seg * 16;
            *(uint4*)(sm + S_AH + off) = hv;
            *(uint4*)(sm + S_AL + off) = lv;
        }
        // --- B chunk: 128 n-rows x 32 k bf16 (pre-split, [n][k]) ---
        #pragma unroll
        for (int i = 0; i < 2; i++) {
            int idx = tid + 256 * i;
            int r = idx >> 2;
            int j = idx & 3;
            const __nv_bfloat16* ph = g_Bh + (size_t)(bn + r) * F_IN + k0 + j * 8;
            const __nv_bfloat16* pl = g_Bl + (size_t)(bn + r) * F_IN + k0 + j * 8;
            uint4 vh = *(const uint4*)ph;
            uint4 vl = *(const uint4*)pl;
            int off = r * ROWB + j * 16;
            *(uint4*)(sm + S_BH + off) = vh;
            *(uint4*)(sm + S_BL + off) = vl;
        }
        __syncthreads();

        #pragma unroll
        for (int ks = 0; ks < 2; ks++) {
            int kbyte = ks * 32;
            // B fragments (hi & lo), 4 n-atoms
            uint32_t bh[4][2], bl[4][2];
            #pragma unroll
            for (int na = 0; na < 4; na++) {
                uint32_t ad = sbase + S_BH +
                    (uint32_t)((wn * 32 + na * 8 + (lane & 7)) * ROWB + kbyte + ((lane >> 3) & 1) * 16);
                LDSM_X2(bh[na][0], bh[na][1], ad);
                LDSM_X2(bl[na][0], bl[na][1], ad + (S_BL - S_BH));
            }
            #pragma unroll
            for (int ma = 0; ma < 4; ma++) {
                uint32_t aad = sbase + S_AH +
                    (uint32_t)((wm * 64 + ma * 16 + (lane & 15)) * ROWB + kbyte + (lane >> 4) * 16);
                uint32_t ah0, ah1, ah2, ah3, al0, al1, al2, al3;
                LDSM_X4(ah0, ah1, ah2, ah3, aad);
                LDSM_X4(al0, al1, al2, al3, aad + (S_AL - S_AH));
                #pragma unroll
                for (int na = 0; na < 4; na++) {
                    MMA_BF16(acc[ma][na][0], acc[ma][na][1], acc[ma][na][2], acc[ma][na][3],
                             ah0, ah1, ah2, ah3, bh[na][0], bh[na][1]);
                    MMA_BF16(acc[ma][na][0], acc[ma][na][1], acc[ma][na][2], acc[ma][na][3],
                             ah0, ah1, ah2, ah3, bl[na][0], bl[na][1]);
                    MMA_BF16(acc[ma][na][0], acc[ma][na][1], acc[ma][na][2], acc[ma][na][3],
                             al0, al1, al2, al3, bh[na][0], bh[na][1]);
                }
            }
        }
        __syncthreads();
    }

    // epilogue: add bias, store fp32
    #pragma unroll
    for (int ma = 0; ma < 4; ma++) {
        int grow0 = bm + wm * 64 + ma * 16 + (lane >> 2);
        int grow1 = grow0 + 8;
        #pragma unroll
        for (int na = 0; na < 4; na++) {
            int col = bn + wn * 32 + na * 8 + (lane & 3) * 2;
            float2 bv = *(const float2*)(bias + col);
            if (grow0 < M) {
                float2 o = make_float2(acc[ma][na][0] + bv.x, acc[ma][na][1] + bv.y);
                *(float2*)(g_H0 + (size_t)grow0 * HID + col) = o;
            }
            if (grow1 < M) {
                float2 o = make_float2(acc[ma][na][2] + bv.x, acc[ma][na][3] + bv.y);
                *(float2*)(g_H0 + (size_t)grow1 * HID + col) = o;
            }
        }
    }
}

// ---------------- fused agg1 + relu + W2 + b2 -> Z (warp per dst) ----------------
__global__ __launch_bounds__(256) void fusedZ_kernel(const float* __restrict__ W2,
                                                     const float* __restrict__ b2) {
    int gw = (blockIdx.x * blockDim.x + threadIdx.x) >> 5;
    int lane = threadIdx.x & 31;
    if (gw >= N_NODES) return;

    int start = g_off[gw];
    int end = start + g_cnt[gw];
    float rdd = g_rdeg[gw];

    int cA = 4 * lane;
    int cB = 128 + 4 * lane;
    float w0a[4], w1a[4], w0b[4], w1b[4];
    #pragma unroll
    for (int j = 0; j < 4; j++) {
        w0a[j] = __ldg(&W2[(cA + j) * 2 + 0]);
        w1a[j] = __ldg(&W2[(cA + j) * 2 + 1]);
        w0b[j] = __ldg(&W2[(cB + j) * 2 + 0]);
        w1b[j] = __ldg(&W2[(cB + j) * 2 + 1]);
    }

    float acc[8] = {};
    int p = start;
    for (; p + 4 <= end; p += 4) {
        int s0 = g_csr_src[p], s1 = g_csr_src[p + 1];
        int s2 = g_csr_src[p + 2], s3 = g_csr_src[p + 3];
        float n0 = rdd * g_rdeg[s0], n1 = rdd * g_rdeg[s1];
        float n2 = rdd * g_rdeg[s2], n3 = rdd * g_rdeg[s3];
        const float4* r0 = (const float4*)(g_H0 + (size_t)s0 * HID);
        const float4* r1 = (const float4*)(g_H0 + (size_t)s1 * HID);
        const float4* r2 = (const float4*)(g_H0 + (size_t)s2 * HID);
        const float4* r3 = (const float4*)(g_H0 + (size_t)s3 * HID);
        float4 a0 = r0[lane], a1 = r0[lane + 32];
        float4 b0 = r1[lane], b1 = r1[lane + 32];
        float4 c0 = r2[lane], c1 = r2[lane + 32];
        float4 d0 = r3[lane], d1 = r3[lane + 32];
        acc[0] += a0.x * n0 + b0.x * n1 + c0.x * n2 + d0.x * n3;
        acc[1] += a0.y * n0 + b0.y * n1 + c0.y * n2 + d0.y * n3;
        acc[2] += a0.z * n0 + b0.z * n1 + c0.z * n2 + d0.z * n3;
        acc[3] += a0.w * n0 + b0.w * n1 + c0.w * n2 + d0.w * n3;
        acc[4] += a1.x * n0 + b1.x * n1 + c1.x * n2 + d1.x * n3;
        acc[5] += a1.y * n0 + b1.y * n1 + c1.y * n2 + d1.y * n3;
        acc[6] += a1.z * n0 + b1.z * n1 + c1.z * n2 + d1.z * n3;
        acc[7] += a1.w * n0 + b1.w * n1 + c1.w * n2 + d1.w * n3;
    }
    for (; p < end; p++) {
        int s0 = g_csr_src[p];
        float n0 = rdd * g_rdeg[s0];
        const float4* r0 = (const float4*)(g_H0 + (size_t)s0 * HID);
        float4 a0 = r0[lane], a1 = r0[lane + 32];
        acc[0] += a0.x * n0; acc[1] += a0.y * n0;
        acc[2] += a0.z * n0; acc[3] += a0.w * n0;
        acc[4] += a1.x * n0; acc[5] += a1.y * n0;
        acc[6] += a1.z * n0; acc[7] += a1.w * n0;
    }

    float z0 = 0.f, z1 = 0.f;
    #pragma unroll
    for (int j = 0; j < 4; j++) {
        float xa = fmaxf(acc[j], 0.f);
        float xb = fmaxf(acc[4 + j], 0.f);
        z0 += xa * w0a[j] + xb * w0b[j];
        z1 += xa * w1a[j] + xb * w1b[j];
    }
    #pragma unroll
    for (int o = 16; o; o >>= 1) {
        z0 += __shfl_down_sync(0xFFFFFFFFu, z0, o);
        z1 += __shfl_down_sync(0xFFFFFFFFu, z1, o);
    }
    if (lane == 0) {
        g_Z[2 * gw + 0] = z0 + b2[0];
        g_Z[2 * gw + 1] = z1 + b2[1];
    }
}

// ---------------- fused agg2 + hyperbolic lift + Poincare projection ----------------
__global__ __launch_bounds__(256) void fusedU_kernel(const float* __restrict__ scale,
                                                     float* __restrict__ out) {
    int gw = (blockIdx.x * blockDim.x + threadIdx.x) >> 5;
    int lane = threadIdx.x & 31;
    if (gw >= N_NODES) return;

    int start = g_off[gw];
    int end = start + g_cnt[gw];
    float rdd = g_rdeg[gw];

    float u0 = 0.f, u1 = 0.f;
    for (int p = start + lane; p < end; p += 32) {
        int s = g_csr_src[p];
        float nm = rdd * g_rdeg[s];
        float2 z = *(const float2*)(g_Z + 2 * s);
        u0 += z.x * nm;
        u1 += z.y * nm;
    }
    #pragma unroll
    for (int o = 16; o; o >>= 1) {
        u0 += __shfl_down_sync(0xFFFFFFFFu, u0, o);
        u1 += __shfl_down_sync(0xFFFFFFFFu, u1, o);
    }
    if (lane == 0) {
        float un = sqrtf(u0 * u0 + u1 * u1);
        un = fmaxf(un, 1e-15f);
        float ch = coshf(un);
        float sh = sinhf(un);
        float inv = 1.0f / (un * (1.0f + ch));
        float p0 = sh * u0 * inv;
        float p1 = sh * u1 * inv;
        float pn = fmaxf(sqrtf(p0 * p0 + p1 * p1), 1e-12f);
        const float MIN_SCALE = 2.0f * (0.999f / 3.0f);
        const float MAX_SCALE = 0.999f;
        float s = fminf(fmaxf(scale[0], MIN_SCALE), MAX_SCALE);
        p0 = p0 / pn * s;
        p1 = p1 / pn * s;
        float nrm = fmaxf(sqrtf(p0 * p0 + p1 * p1), 1e-15f);
        float maxnorm = 1.0f - 1e-15f;
        if (nrm > maxnorm) {
            p0 = p0 / nrm * maxnorm;
            p1 = p1 / nrm * maxnorm;
        }
        out[2 * gw + 0] = p0;
        out[2 * gw + 1] = p1;
    }
}

// ---------------- launch ----------------
extern "C" void kernel_launch(void* const* d_in, const int* in_sizes, int n_in,
                              void* d_out, int out_size) {
    const float* feature = (const float*)d_in[0];
    const int* ei = (const int*)d_in[1];
    const float* W1 = (const float*)d_in[2];
    const float* b1 = (const float*)d_in[3];
    const float* W2 = (const float*)d_in[4];
    const float* b2 = (const float*)d_in[5];
    const float* scale = (const float*)d_in[6];
    float* out = (float*)d_out;

    zero_kernel<<<(N_NODES + 255) / 256, 256>>>();
    deg_kernel<<<(N_EDGES + 255) / 256, 256>>>(ei);
    scan_kernel<<<1, SCAN_THREADS>>>();
    scatter_kernel<<<(N_EDGES + 255) / 256, 256>>>(ei);
    prepW_kernel<<<(F_IN * HID + 255) / 256, 256>>>(W1);
    {
        dim3 grid(HID / 128, (N_NODES + 127) / 128);   // (2, 79)
        gemm_mma_kernel<<<grid, 256>>>(feature, b1);
    }
    fusedZ_kernel<<<(N_NODES * 32 + 255) / 256, 256>>>(W2, b2);
    fusedU_kernel<<<(N_NODES * 32 + 255) / 256, 256>>>(scale, out);
}

// round 7
// speedup vs baseline: 1.8356x; 1.1901x over previous
#include <cuda_runtime.h>
#include <cuda_bf16.h>
#include <cstdint>

#define N_NODES 10000
#define N_EDGES 320000
#define F_IN 512
#define HID 256
#define M_PAD 10112         // 10000 rounded up to 128
#define BKT 128             // bucket capacity per node

// ---------------- device scratch (static, no allocation) ----------------
__device__ __align__(16) int   g_pos[N_NODES];                 // fill counter == indegree
__device__ __align__(16) float g_rdeg[N_NODES];
__device__ __align__(16) int   g_bkt[(size_t)N_NODES * BKT];   // src ids per dst
__device__ __align__(16) float g_H0[(size_t)N_NODES * HID];
__device__ __align__(16) float g_Z[N_NODES * 2];
__device__ __align__(16) __nv_bfloat16 g_Ah[(size_t)M_PAD * F_IN];
__device__ __align__(16) __nv_bfloat16 g_Al[(size_t)M_PAD * F_IN];
__device__ __align__(16) __nv_bfloat16 g_Bh[HID * F_IN];       // W1^T hi [n][k]
__device__ __align__(16) __nv_bfloat16 g_Bl[HID * F_IN];       // W1^T lo [n][k]

// ---------------- mma/ldmatrix/cp.async helpers (base ISA, sm_80+) ----------------
#define LDSM_X4(r0, r1, r2, r3, addr) \
    asm volatile("ldmatrix.sync.aligned.m8n8.x4.shared.b16 {%0,%1,%2,%3}, [%4];" \
        : "=r"(r0), "=r"(r1), "=r"(r2), "=r"(r3) : "r"(addr))
#define LDSM_X2(r0, r1, addr) \
    asm volatile("ldmatrix.sync.aligned.m8n8.x2.shared.b16 {%0,%1}, [%2];" \
        : "=r"(r0), "=r"(r1) : "r"(addr))
#define MMA_BF16(d0, d1, d2, d3, a0, a1, a2, a3, b0, b1) \
    asm volatile("mma.sync.aligned.m16n8k16.row.col.f32.bf16.bf16.f32 " \
        "{%0,%1,%2,%3}, {%4,%5,%6,%7}, {%8,%9}, {%0,%1,%2,%3};" \
        : "+f"(d0), "+f"(d1), "+f"(d2), "+f"(d3) \
        : "r"(a0), "r"(a1), "r"(a2), "r"(a3), "r"(b0), "r"(b1))
#define CP16(saddr, gptr) \
    asm volatile("cp.async.cg.shared.global [%0], [%1], 16;" :: "r"(saddr), "l"(gptr))
#define CP_COMMIT() asm volatile("cp.async.commit_group;" ::: "memory")
#define CP_WAIT1()  asm volatile("cp.async.wait_group 1;" ::: "memory")

// ---------------- zero fill counters ----------------
__global__ void zero_kernel() {
    int i = blockIdx.x * blockDim.x + threadIdx.x;
    if (i < N_NODES) g_pos[i] = 0;
}

// ---------------- bucket scatter (no scan needed) ----------------
__global__ void scatter_kernel(const int* __restrict__ ei) {
    int e = blockIdx.x * blockDim.x + threadIdx.x;
    if (e >= N_EDGES) return;
    int s = ei[e];
    int d = ei[N_EDGES + e];
    int pos = atomicAdd(&g_pos[d], 1);
    if (pos < BKT) g_bkt[(size_t)d * BKT + pos] = s;
}

// ---------------- rdeg ----------------
__global__ void rdeg_kernel() {
    int i = blockIdx.x * blockDim.x + threadIdx.x;
    if (i < N_NODES) g_rdeg[i] = rsqrtf(fmaxf((float)g_pos[i], 1.0f));
}

// ---------------- prep: bf16-split A, and transpose+split W1 ----------------
__global__ void prep_kernel(const float* __restrict__ A, const float* __restrict__ W1) {
    int tid = blockIdx.x * blockDim.x + threadIdx.x;
    // A part: 5,120,000 elements, 8 per thread -> 640,000 threads
    if (tid < (N_NODES * F_IN) / 8) {
        int idx8 = tid * 8;
        const float* p = A + idx8;
        float4 v0 = *(const float4*)p;
        float4 v1 = *(const float4*)(p + 4);
        float vals[8] = {v0.x, v0.y, v0.z, v0.w, v1.x, v1.y, v1.z, v1.w};
        uint32_t hw[4], lw[4];
        #pragma unroll
        for (int q = 0; q < 4; q++) {
            __nv_bfloat16 h0 = __float2bfloat16_rn(vals[2 * q]);
            __nv_bfloat16 h1 = __float2bfloat16_rn(vals[2 * q + 1]);
            float r0 = vals[2 * q] - __bfloat162float(h0);
            float r1 = vals[2 * q + 1] - __bfloat162float(h1);
            __nv_bfloat16 l0 = __float2bfloat16_rn(r0);
            __nv_bfloat16 l1 = __float2bfloat16_rn(r1);
            hw[q] = (uint32_t)*(unsigned short*)&h0 | ((uint32_t)*(unsigned short*)&h1 << 16);
            lw[q] = (uint32_t)*(unsigned short*)&l0 | ((uint32_t)*(unsigned short*)&l1 << 16);
        }
        *(uint4*)(g_Ah + idx8) = make_uint4(hw[0], hw[1], hw[2], hw[3]);
        *(uint4*)(g_Al + idx8) = make_uint4(lw[0], lw[1], lw[2], lw[3]);
    }
    // W part: 131072 elements -> 16384 threads x 8 (transpose [k][n] -> [n][k])
    if (tid < (F_IN * HID) / 8) {
        int n = tid & 255;
        int kb = (tid >> 8) * 8;
        uint32_t hw[4], lw[4];
        #pragma unroll
        for (int q = 0; q < 4; q++) {
            float x0 = W1[(size_t)(kb + 2 * q) * HID + n];
            float x1 = W1[(size_t)(kb + 2 * q + 1) * HID + n];
            __nv_bfloat16 h0 = __float2bfloat16_rn(x0);
            __nv_bfloat16 h1 = __float2bfloat16_rn(x1);
            float r0 = x0 - __bfloat162float(h0);
            float r1 = x1 - __bfloat162float(h1);
            __nv_bfloat16 l0 = __float2bfloat16_rn(r0);
            __nv_bfloat16 l1 = __float2bfloat16_rn(r1);
            hw[q] = (uint32_t)*(unsigned short*)&h0 | ((uint32_t)*(unsigned short*)&h1 << 16);
            lw[q] = (uint32_t)*(unsigned short*)&l0 | ((uint32_t)*(unsigned short*)&l1 << 16);
        }
        *(uint4*)(g_Bh + (size_t)n * F_IN + kb) = make_uint4(hw[0], hw[1], hw[2], hw[3]);
        *(uint4*)(g_Bl + (size_t)n * F_IN + kb) = make_uint4(lw[0], lw[1], lw[2], lw[3]);
    }
}

// ---------------- HMMA GEMM, cp.async double-buffered ----------------
// CTA tile 128x128, 8 warps (2M x 4N), warp tile 64x32, K chunks of 32, 16 chunks.
// SMEM per stage: Ah/Al/Bh/Bl each 128 rows x 80B = 10240B -> 40960B; 2 stages.
#define ROWB 80
#define STG 40960
#define S_AH 0
#define S_AL 10240
#define S_BH 20480
#define S_BL 30720

__global__ __launch_bounds__(256, 2) void gemm_mma_kernel(const float* __restrict__ bias) {
    extern __shared__ __align__(128) char sm[];
    uint32_t sbase = (uint32_t)__cvta_generic_to_shared(sm);

    const int M = N_NODES;
    int tid = threadIdx.x;
    int wid = tid >> 5;
    int lane = tid & 31;
    int wm = wid >> 2;
    int wn = wid & 3;
    int bm = blockIdx.y * 128;
    int bn = blockIdx.x * 128;

    // per-thread cp.async mapping: 2 iterations x (r = idx>>2, j = idx&3)
    int r0i = tid >> 2, j0 = tid & 3;
    int r1i = (tid + 256) >> 2, j1 = tid & 3;

    float acc[4][4][4];
    #pragma unroll
    for (int i = 0; i < 4; i++)
        #pragma unroll
        for (int j = 0; j < 4; j++)
            #pragma unroll
            for (int r = 0; r < 4; r++) acc[i][j][r] = 0.f;

    auto load_stage = [&](int c, int s) {
        int k0 = c * 32;
        uint32_t sb = sbase + s * STG;
        const char* gAh = (const char*)(g_Ah + (size_t)bm * F_IN + k0);
        const char* gAl = (const char*)(g_Al + (size_t)bm * F_IN + k0);
        const char* gBh = (const char*)(g_Bh + (size_t)bn * F_IN + k0);
        const char* gBl = (const char*)(g_Bl + (size_t)bn * F_IN + k0);
        // i = 0
        {
            int r = r0i, j = j0;
            size_t go = (size_t)r * (F_IN * 2) + j * 16;
            uint32_t so = r * ROWB + j * 16;
            CP16(sb + S_AH + so, gAh + go);
            CP16(sb + S_AL + so, gAl + go);
            CP16(sb + S_BH + so, gBh + go);
            CP16(sb + S_BL + so, gBl + go);
        }
        // i = 1
        {
            int r = r1i, j = j1;
            size_t go = (size_t)r * (F_IN * 2) + j * 16;
            uint32_t so = r * ROWB + j * 16;
            CP16(sb + S_AH + so, gAh + go);
            CP16(sb + S_AL + so, gAl + go);
            CP16(sb + S_BH + so, gBh + go);
            CP16(sb + S_BL + so, gBl + go);
        }
    };

    load_stage(0, 0);
    CP_COMMIT();

    for (int c = 0; c < 16; c++) {
        int s = c & 1;
        if (c + 1 < 16) load_stage(c + 1, (c + 1) & 1);
        CP_COMMIT();
        CP_WAIT1();
        __syncthreads();

        uint32_t stb = sbase + s * STG;
        #pragma unroll
        for (int ks = 0; ks < 2; ks++) {
            int kbyte = ks * 32;
            uint32_t bh[4][2], bl[4][2];
            #pragma unroll
            for (int na = 0; na < 4; na++) {
                uint32_t ad = stb + S_BH +
                    (uint32_t)((wn * 32 + na * 8 + (lane & 7)) * ROWB + kbyte + ((lane >> 3) & 1) * 16);
                LDSM_X2(bh[na][0], bh[na][1], ad);
                LDSM_X2(bl[na][0], bl[na][1], ad + (S_BL - S_BH));
            }
            #pragma unroll
            for (int ma = 0; ma < 4; ma++) {
                uint32_t aad = stb + S_AH +
                    (uint32_t)((wm * 64 + ma * 16 + (lane & 15)) * ROWB + kbyte + (lane >> 4) * 16);
                uint32_t ah0, ah1, ah2, ah3, al0, al1, al2, al3;
                LDSM_X4(ah0, ah1, ah2, ah3, aad);
                LDSM_X4(al0, al1, al2, al3, aad + (S_AL - S_AH));
                #pragma unroll
                for (int na = 0; na < 4; na++) {
                    MMA_BF16(acc[ma][na][0], acc[ma][na][1], acc[ma][na][2], acc[ma][na][3],
                             ah0, ah1, ah2, ah3, bh[na][0], bh[na][1]);
                    MMA_BF16(acc[ma][na][0], acc[ma][na][1], acc[ma][na][2], acc[ma][na][3],
                             ah0, ah1, ah2, ah3, bl[na][0], bl[na][1]);
                    MMA_BF16(acc[ma][na][0], acc[ma][na][1], acc[ma][na][2], acc[ma][na][3],
                             al0, al1, al2, al3, bh[na][0], bh[na][1]);
                }
            }
        }
        __syncthreads();
    }

    // epilogue: add bias, store fp32
    #pragma unroll
    for (int ma = 0; ma < 4; ma++) {
        int grow0 = bm + wm * 64 + ma * 16 + (lane >> 2);
        int grow1 = grow0 + 8;
        #pragma unroll
        for (int na = 0; na < 4; na++) {
            int col = bn + wn * 32 + na * 8 + (lane & 3) * 2;
            float2 bv = *(const float2*)(bias + col);
            if (grow0 < M) {
                float2 o = make_float2(acc[ma][na][0] + bv.x, acc[ma][na][1] + bv.y);
                *(float2*)(g_H0 + (size_t)grow0 * HID + col) = o;
            }
            if (grow1 < M) {
                float2 o = make_float2(acc[ma][na][2] + bv.x, acc[ma][na][3] + bv.y);
                *(float2*)(g_H0 + (size_t)grow1 * HID + col) = o;
            }
        }
    }
}

// ---------------- fused agg1 + relu + W2 + b2 -> Z (warp per dst) ----------------
__global__ __launch_bounds__(256) void fusedZ_kernel(const float* __restrict__ W2,
                                                     const float* __restrict__ b2) {
    int gw = (blockIdx.x * blockDim.x + threadIdx.x) >> 5;
    int lane = threadIdx.x & 31;
    if (gw >= N_NODES) return;

    int cnt = g_pos[gw];
    if (cnt > BKT) cnt = BKT;
    const int* bkt = g_bkt + (size_t)gw * BKT;
    float rdd = g_rdeg[gw];

    int cA = 4 * lane;
    int cB = 128 + 4 * lane;
    float w0a[4], w1a[4], w0b[4], w1b[4];
    #pragma unroll
    for (int j = 0; j < 4; j++) {
        w0a[j] = __ldg(&W2[(cA + j) * 2 + 0]);
        w1a[j] = __ldg(&W2[(cA + j) * 2 + 1]);
        w0b[j] = __ldg(&W2[(cB + j) * 2 + 0]);
        w1b[j] = __ldg(&W2[(cB + j) * 2 + 1]);
    }

    float acc[8] = {};
    int p = 0;
    for (; p + 4 <= cnt; p += 4) {
        int s0 = bkt[p], s1 = bkt[p + 1], s2 = bkt[p + 2], s3 = bkt[p + 3];
        float n0 = rdd * g_rdeg[s0], n1 = rdd * g_rdeg[s1];
        float n2 = rdd * g_rdeg[s2], n3 = rdd * g_rdeg[s3];
        const float4* r0 = (const float4*)(g_H0 + (size_t)s0 * HID);
        const float4* r1 = (const float4*)(g_H0 + (size_t)s1 * HID);
        const float4* r2 = (const float4*)(g_H0 + (size_t)s2 * HID);
        const float4* r3 = (const float4*)(g_H0 + (size_t)s3 * HID);
        float4 a0 = r0[lane], a1 = r0[lane + 32];
        float4 b0 = r1[lane], b1 = r1[lane + 32];
        float4 c0 = r2[lane], c1 = r2[lane + 32];
        float4 d0 = r3[lane], d1 = r3[lane + 32];
        acc[0] += a0.x * n0 + b0.x * n1 + c0.x * n2 + d0.x * n3;
        acc[1] += a0.y * n0 + b0.y * n1 + c0.y * n2 + d0.y * n3;
        acc[2] += a0.z * n0 + b0.z * n1 + c0.z * n2 + d0.z * n3;
        acc[3] += a0.w * n0 + b0.w * n1 + c0.w * n2 + d0.w * n3;
        acc[4] += a1.x * n0 + b1.x * n1 + c1.x * n2 + d1.x * n3;
        acc[5] += a1.y * n0 + b1.y * n1 + c1.y * n2 + d1.y * n3;
        acc[6] += a1.z * n0 + b1.z * n1 + c1.z * n2 + d1.z * n3;
        acc[7] += a1.w * n0 + b1.w * n1 + c1.w * n2 + d1.w * n3;
    }
    for (; p < cnt; p++) {
        int s0 = bkt[p];
        float n0 = rdd * g_rdeg[s0];
        const float4* r0 = (const float4*)(g_H0 + (size_t)s0 * HID);
        float4 a0 = r0[lane], a1 = r0[lane + 32];
        acc[0] += a0.x * n0; acc[1] += a0.y * n0;
        acc[2] += a0.z * n0; acc[3] += a0.w * n0;
        acc[4] += a1.x * n0; acc[5] += a1.y * n0;
        acc[6] += a1.z * n0; acc[7] += a1.w * n0;
    }

    float z0 = 0.f, z1 = 0.f;
    #pragma unroll
    for (int j = 0; j < 4; j++) {
        float xa = fmaxf(acc[j], 0.f);
        float xb = fmaxf(acc[4 + j], 0.f);
        z0 += xa * w0a[j] + xb * w0b[j];
        z1 += xa * w1a[j] + xb * w1b[j];
    }
    #pragma unroll
    for (int o = 16; o; o >>= 1) {
        z0 += __shfl_down_sync(0xFFFFFFFFu, z0, o);
        z1 += __shfl_down_sync(0xFFFFFFFFu, z1, o);
    }
    if (lane == 0) {
        g_Z[2 * gw + 0] = z0 + b2[0];
        g_Z[2 * gw + 1] = z1 + b2[1];
    }
}

// ---------------- fused agg2 + hyperbolic lift + Poincare projection ----------------
__global__ __launch_bounds__(256) void fusedU_kernel(const float* __restrict__ scale,
                                                     float* __restrict__ out) {
    int gw = (blockIdx.x * blockDim.x + threadIdx.x) >> 5;
    int lane = threadIdx.x & 31;
    if (gw >= N_NODES) return;

    int cnt = g_pos[gw];
    if (cnt > BKT) cnt = BKT;
    const int* bkt = g_bkt + (size_t)gw * BKT;
    float rdd = g_rdeg[gw];

    float u0 = 0.f, u1 = 0.f;
    for (int p = lane; p < cnt; p += 32) {
        int s = bkt[p];
        float nm = rdd * g_rdeg[s];
        float2 z = *(const float2*)(g_Z + 2 * s);
        u0 += z.x * nm;
        u1 += z.y * nm;
    }
    #pragma unroll
    for (int o = 16; o; o >>= 1) {
        u0 += __shfl_down_sync(0xFFFFFFFFu, u0, o);
        u1 += __shfl_down_sync(0xFFFFFFFFu, u1, o);
    }
    if (lane == 0) {
        float un = sqrtf(u0 * u0 + u1 * u1);
        un = fmaxf(un, 1e-15f);
        float ch = coshf(un);
        float sh = sinhf(un);
        float inv = 1.0f / (un * (1.0f + ch));
        float p0 = sh * u0 * inv;
        float p1 = sh * u1 * inv;
        float pn = fmaxf(sqrtf(p0 * p0 + p1 * p1), 1e-12f);
        const float MIN_SCALE = 2.0f * (0.999f / 3.0f);
        const float MAX_SCALE = 0.999f;
        float s = fminf(fmaxf(scale[0], MIN_SCALE), MAX_SCALE);
        p0 = p0 / pn * s;
        p1 = p1 / pn * s;
        float nrm = fmaxf(sqrtf(p0 * p0 + p1 * p1), 1e-15f);
        float maxnorm = 1.0f - 1e-15f;
        if (nrm > maxnorm) {
            p0 = p0 / nrm * maxnorm;
            p1 = p1 / nrm * maxnorm;
        }
        out[2 * gw + 0] = p0;
        out[2 * gw + 1] = p1;
    }
}

// ---------------- launch ----------------
extern "C" void kernel_launch(void* const* d_in, const int* in_sizes, int n_in,
                              void* d_out, int out_size) {
    const float* feature = (const float*)d_in[0];
    const int* ei = (const int*)d_in[1];
    const float* W1 = (const float*)d_in[2];
    const float* b1 = (const float*)d_in[3];
    const float* W2 = (const float*)d_in[4];
    const float* b2 = (const float*)d_in[5];
    const float* scale = (const float*)d_in[6];
    float* out = (float*)d_out;

    cudaFuncSetAttribute(gemm_mma_kernel,
                         cudaFuncAttributeMaxDynamicSharedMemorySize, 2 * STG);

    zero_kernel<<<(N_NODES + 255) / 256, 256>>>();
    scatter_kernel<<<(N_EDGES + 255) / 256, 256>>>(ei);
    rdeg_kernel<<<(N_NODES + 255) / 256, 256>>>();
    prep_kernel<<<((N_NODES * F_IN / 8) + 255) / 256, 256>>>(feature, W1);
    {
        dim3 grid(HID / 128, (N_NODES + 127) / 128);   // (2, 79)
        gemm_mma_kernel<<<grid, 256, 2 * STG>>>(b1);
    }
    fusedZ_kernel<<<(N_NODES * 32 + 255) / 256, 256>>>(W2, b2);
    fusedU_kernel<<<(N_NODES * 32 + 255) / 256, 256>>>(scale, out);
}